// round 2
// baseline (speedup 1.0000x reference)
#include <cuda_runtime.h>
#include <cstdint>

// 26 node coordinates (compile-time __constant__ init; no runtime copy)
__constant__ float2 c_nodes[26] = {
    {0.5454545454545454f, 0.76f}, {0.6022727272727273f, 0.76f},
    {0.5454545454545454f, 0.86f}, {0.6022727272727273f, 0.86f},
    {0.4772727272727273f, 0.76f}, {0.42045454545454547f, 0.76f},
    {0.42045454545454547f, 0.86f}, {0.4772727272727273f, 0.86f},
    {0.32954545454545453f, 0.808f}, {0.42045454545454547f, 0.48f},
    {0.4772727272727273f, 0.48f}, {0.4772727272727273f, 0.38f},
    {0.42045454545454547f, 0.38f}, {0.32954545454545453f, 0.428f},
    {0.5727272727272728f, 0.62f}, {0.7613636363636364f, 0.76f},
    {0.8181818181818182f, 0.76f}, {0.8181818181818182f, 0.86f},
    {0.7613636363636364f, 0.86f}, {0.7909090909090909f, 0.62f},
    {0.9431818181818182f, 0.76f}, {1.0f, 0.76f},
    {1.0f, 0.86f}, {0.9431818181818182f, 0.86f},
    {0.9727272727272728f, 0.62f}, {0.9727272727272728f, 1.0f}
};

// Output row = 272 floats:
//   [0:6)=x[0:6], [6:134)=emb[idx1], [134:138)=x[6:10),
//   [138:266)=emb[idx2], [266:272)=x[10:16)
// As 68 float4s (f = 4c):
//   c in [2,32]  : fully inside emb1 (e1[f-6 .. f-3])
//   c in [35,65] : fully inside emb2 (e2[f-138 .. f-135])
//   c in {0,1,33,34,66,67} : boundary, scalar gather

__device__ __forceinline__ float fetch_one(int f, const float* __restrict__ xr,
                                           const float* __restrict__ e1,
                                           const float* __restrict__ e2)
{
    if (f < 6)   return xr[f];
    if (f < 134) return e1[f - 6];
    if (f < 138) return xr[f - 128];
    if (f < 266) return e2[f - 138];
    return xr[f - 256];
}

__global__ __launch_bounds__(256) void pe_kernel(
    const float* __restrict__ x,
    const float* __restrict__ emb,
    float* __restrict__ out,
    int rows)
{
    int gwarp = (blockIdx.x * blockDim.x + threadIdx.x) >> 5;
    int lane  = threadIdx.x & 31;
    if (gwarp >= rows) return;

    const float* xr = x + (size_t)gwarp * 16;
    // x[4..7] as one aligned float4 (row base 64B-aligned), x[8..9] as float2
    float4 x47 = *reinterpret_cast<const float4*>(xr + 4);
    float2 pt1 = make_float2(x47.x, x47.y);
    float2 pt2 = *reinterpret_cast<const float2*>(xr + 8);

    bool m1 = false, m2 = false;
    if (lane < 26) {
        float2 n = c_nodes[lane];
        float tx = 0.01f + 1e-5f * fabsf(n.x);
        float ty = 0.01f + 1e-5f * fabsf(n.y);
        m1 = (fabsf(pt1.x - n.x) <= tx) && (fabsf(pt1.y - n.y) <= ty);
        m2 = (fabsf(pt2.x - n.x) <= tx) && (fabsf(pt2.y - n.y) <= ty);
    }
    unsigned b1 = __ballot_sync(0xffffffffu, m1);
    unsigned b2 = __ballot_sync(0xffffffffu, m2);
    int idx1 = __ffs(b1);   // 1-based ffs == reference's argmax+1; 0 if no match
    int idx2 = __ffs(b2);

    const float* e1 = emb + (size_t)idx1 * 128;
    const float* e2 = emb + (size_t)idx2 * 128;
    float4* o = reinterpret_cast<float4*>(out + (size_t)gwarp * 272);

    #pragma unroll
    for (int i = 0; i < 3; i++) {
        int c = lane + i * 32;
        if (c < 68) {
            int f = 4 * c;
            float4 v;
            if (c >= 2 && c <= 32) {
                const float2* p = reinterpret_cast<const float2*>(e1 + (f - 6));
                float2 a = p[0], b = p[1];
                v = make_float4(a.x, a.y, b.x, b.y);
            } else if (c >= 35 && c <= 65) {
                const float2* p = reinterpret_cast<const float2*>(e2 + (f - 138));
                float2 a = p[0], b = p[1];
                v = make_float4(a.x, a.y, b.x, b.y);
            } else {
                v.x = fetch_one(f + 0, xr, e1, e2);
                v.y = fetch_one(f + 1, xr, e1, e2);
                v.z = fetch_one(f + 2, xr, e1, e2);
                v.w = fetch_one(f + 3, xr, e1, e2);
            }
            o[c] = v;
        }
    }
}

extern "C" void kernel_launch(void* const* d_in, const int* in_sizes, int n_in,
                              void* d_out, int out_size)
{
    const float* x;
    const float* emb;
    int xsz;
    if (in_sizes[0] > in_sizes[1]) {
        x = (const float*)d_in[0]; emb = (const float*)d_in[1]; xsz = in_sizes[0];
    } else {
        x = (const float*)d_in[1]; emb = (const float*)d_in[0]; xsz = in_sizes[1];
    }
    int rows = xsz / 16;                  // 262144
    int blocks = (rows * 32 + 255) / 256; // 8 warps/block, 1 row/warp
    pe_kernel<<<blocks, 256>>>(x, emb, (float*)d_out, rows);
}

// round 3
// speedup vs baseline: 1.3969x; 1.3969x over previous
#include <cuda_runtime.h>
#include <cstdint>

// 26 node coordinates (compile-time __constant__ init; no runtime copy)
__constant__ float2 c_nodes[26] = {
    {0.5454545454545454f, 0.76f}, {0.6022727272727273f, 0.76f},
    {0.5454545454545454f, 0.86f}, {0.6022727272727273f, 0.86f},
    {0.4772727272727273f, 0.76f}, {0.42045454545454547f, 0.76f},
    {0.42045454545454547f, 0.86f}, {0.4772727272727273f, 0.86f},
    {0.32954545454545453f, 0.808f}, {0.42045454545454547f, 0.48f},
    {0.4772727272727273f, 0.48f}, {0.4772727272727273f, 0.38f},
    {0.42045454545454547f, 0.38f}, {0.32954545454545453f, 0.428f},
    {0.5727272727272728f, 0.62f}, {0.7613636363636364f, 0.76f},
    {0.8181818181818182f, 0.76f}, {0.8181818181818182f, 0.86f},
    {0.7613636363636364f, 0.86f}, {0.7909090909090909f, 0.62f},
    {0.9431818181818182f, 0.76f}, {1.0f, 0.76f},
    {1.0f, 0.86f}, {0.9431818181818182f, 0.86f},
    {0.9727272727272728f, 0.62f}, {0.9727272727272728f, 1.0f}
};

// Output row = 272 floats = 136 float2:
//   c in [0,3)    -> x2[c]
//   c in [3,67)   -> e1[c-3]
//   c in [67,69)  -> x2[c-64]
//   c in [69,133) -> e2[c-69]
//   c in [133,136)-> x2[c-128]

constexpr int ROWS_PER_BLOCK = 64;   // 64 rows * 16 floats = 4KB smem
constexpr int THREADS = 256;         // 8 warps; 8 rows per warp

__global__ __launch_bounds__(THREADS) void pe_kernel(
    const float* __restrict__ x,
    const float* __restrict__ emb,
    float* __restrict__ out,
    int rows)
{
    __shared__ float4 s4[ROWS_PER_BLOCK * 16 / 4];   // 256 float4

    int block_row0 = blockIdx.x * ROWS_PER_BLOCK;

    // Stage x for 64 rows: one coalesced float4 per thread (high MLP, paid once)
    {
        size_t fidx = (size_t)block_row0 * 4 + threadIdx.x;   // float4 index
        if ((int)(fidx / 4) < rows)                            // row guard
            s4[threadIdx.x] = reinterpret_cast<const float4*>(x)[fidx];
    }
    __syncthreads();
    const float* sx = reinterpret_cast<const float*>(s4);

    int warp = threadIdx.x >> 5;
    int lane = threadIdx.x & 31;

    // Per-lane node + tolerance (lanes 0..25 active)
    bool active = lane < 26;
    float nx = 0.f, ny = 0.f, tx = -1.f, ty = -1.f;
    if (active) {
        float2 n = c_nodes[lane];
        nx = n.x; ny = n.y;
        tx = 0.01f + 1e-5f * fabsf(nx);
        ty = 0.01f + 1e-5f * fabsf(ny);
    }

    #pragma unroll 2
    for (int r8 = 0; r8 < 8; r8++) {
        int r = warp * 8 + r8;                 // row within block
        int grow = block_row0 + r;
        if (grow >= rows) break;

        const float* xr = sx + r * 16;
        float2 pt1 = *reinterpret_cast<const float2*>(xr + 4);   // LDS broadcast
        float2 pt2 = *reinterpret_cast<const float2*>(xr + 8);

        bool m1 = active && (fabsf(pt1.x - nx) <= tx) && (fabsf(pt1.y - ny) <= ty);
        bool m2 = active && (fabsf(pt2.x - nx) <= tx) && (fabsf(pt2.y - ny) <= ty);
        int idx1 = __ffs(__ballot_sync(0xffffffffu, m1));  // 1-based == argmax+1; 0 if none
        int idx2 = __ffs(__ballot_sync(0xffffffffu, m2));

        const float2* e1 = reinterpret_cast<const float2*>(emb + (size_t)idx1 * 128);
        const float2* e2 = reinterpret_cast<const float2*>(emb + (size_t)idx2 * 128);
        const float2* x2 = reinterpret_cast<const float2*>(xr);
        float2* o = reinterpret_cast<float2*>(out + (size_t)grow * 272);

        #pragma unroll
        for (int i = 0; i < 5; i++) {
            int c = lane + i * 32;
            if (i < 4 || c < 136) {
                float2 v;
                if (c < 3)        v = x2[c];          // smem
                else if (c < 67)  v = e1[c - 3];      // L1-resident, 8B-aligned
                else if (c < 69)  v = x2[c - 64];
                else if (c < 133) v = e2[c - 69];
                else              v = x2[c - 128];
                o[c] = v;                              // coalesced STG.64
            }
        }
    }
}

extern "C" void kernel_launch(void* const* d_in, const int* in_sizes, int n_in,
                              void* d_out, int out_size)
{
    const float* x;
    const float* emb;
    int xsz;
    if (in_sizes[0] > in_sizes[1]) {
        x = (const float*)d_in[0]; emb = (const float*)d_in[1]; xsz = in_sizes[0];
    } else {
        x = (const float*)d_in[1]; emb = (const float*)d_in[0]; xsz = in_sizes[1];
    }
    int rows = xsz / 16;                                    // 262144
    int blocks = (rows + ROWS_PER_BLOCK - 1) / ROWS_PER_BLOCK;  // 4096
    pe_kernel<<<blocks, THREADS>>>(x, emb, (float*)d_out, rows);
}